// round 11
// baseline (speedup 1.0000x reference)
#include <cuda_runtime.h>

#define NGRID 20
#define NPTS  8000           // 20^3
#define TD    39             // offsets -19..19
#define DA_MAX 7             // da^2/2 > 28 -> plane pruned
#define D2_CUT 28.0f

// Scratch (no allocation allowed in kernel_launch)
__device__ float g_partial[NGRID * NPTS];   // [ib][pt]
__device__ float g_bsum[NGRID * NGRID];     // per live (ia,ib) pair sum
__device__ int   g_cnt_ia[NGRID];           // pairs done per ia-plane
__device__ int   g_cnt_pl;                  // planes gathered

// ---------------------------------------------------------------------------
// Single kernel, decoupled-completion epilogue:
//  * 400 blocks (244 live), one (ia,ib) pair each — conv body identical to
//    the R10-validated version.
//  * fence + atomicAdd(cnt_ia[ia]); the pair that completes its plane gathers
//    that plane from L2-hot partials into out (unnormalized).
//  * fence + atomicAdd(cnt_pl); the 20th plane-finisher computes S (fixed
//    order) and divides out in place, then resets counters (replay-safe).
//  No spinning anywhere; deterministic value computation throughout.
// ---------------------------------------------------------------------------
__global__ void __launch_bounds__(400) kde_kernel(
    const float* __restrict__ p, const float* __restrict__ cov_inv,
    float* __restrict__ out)
{
    __shared__ __align__(16) float sT[TD * TD + 3];
    __shared__ __align__(16) float sp[NGRID * NGRID];
    __shared__ __align__(16) float sred[1600];
    __shared__ int   sflag;
    __shared__ float sS;

    const int t  = threadIdx.x;
    const int ia = blockIdx.x;
    const int ib = blockIdx.y;
    const int da = ia - ib;

    if (da < -DA_MAX || da > DA_MAX) return;   // pruned: touches nothing

    const float a00 = cov_inv[0], a01 = cov_inv[1], a02 = cov_inv[2];
    const float a11 = cov_inv[4], a12 = cov_inv[5], a22 = cov_inv[8];

    sp[t] = p[ib * 400 + t];

    if (t < 156) {     // table slab via 2-FMUL exp recurrence
        int row = t >> 2, seg = t & 3;
        float dy = (float)(row - 19);
        int   dz0 = -19 + seg * 10;
        int   cnt = (seg == 3) ? 9 : 10;
        float dx = (float)da;
        float c1 = 2.0f * (a02 * dx + a12 * dy);
        float c0 = a00 * dx * dx + 2.0f * a01 * dx * dy + a11 * dy * dy;
        float z  = (float)dz0;
        float g  = expf(-0.5f * (c0 + c1 * z + a22 * z * z));
        float r  = expf(-0.5f * (c1 + a22 * (2.0f * z + 1.0f)));
        float B  = expf(-a22);
        float* dst = &sT[row * TD + (dz0 + 19)];
        for (int i = 0; i < cnt; i++) { dst[i] = g; g *= r; r *= B; }
    }
    __syncthreads();

    const int gidx = t / 100;
    const int s    = t - gidx * 100;
    const int ja   = s / 5;
    const int ka0  = (s - ja * 5) * 4;

    float s00 = a00 - a02 * a02 / a22;
    float s01 = a01 - a02 * a12 / a22;
    float s11 = a11 - a12 * a12 / a22;
    float fx  = (float)da;
    float bq  = s01 * fx;
    float disc = bq * bq - s11 * (s00 * fx * fx - D2_CUT);
    int jb_lo = 0, jb_hi = -1;
    if (disc > 0.0f) {
        float sq  = sqrtf(disc);
        float dyl = (-bq - sq) / s11;
        float dyh = (-bq + sq) / s11;
        jb_lo = max(0,  (int)ceilf ((float)ja - dyh - 0.01f));
        jb_hi = min(19, (int)floorf((float)ja - dyl + 0.01f));
    }

    float acc0 = 0.f, acc1 = 0.f, acc2 = 0.f, acc3 = 0.f;

    for (int jb = jb_lo + gidx; jb <= jb_hi; jb += 4) {
        const float* row = &sT[(ja - jb + 19) * TD];

        float pv[20];
        {
            const float4* pr4 = reinterpret_cast<const float4*>(&sp[jb * NGRID]);
#pragma unroll
            for (int u = 0; u < 5; u++) {
                float4 v = pr4[u];
                pv[4*u] = v.x; pv[4*u+1] = v.y; pv[4*u+2] = v.z; pv[4*u+3] = v.w;
            }
        }

        float w0 = row[ka0 + 19];
        float w1 = row[ka0 + 20];
        float w2 = row[ka0 + 21];
        float w3 = row[ka0 + 22];
#pragma unroll
        for (int kb = 0; kb < 20; kb++) {
            float pvk = pv[kb];
            acc0 = fmaf(w0, pvk, acc0);
            acc1 = fmaf(w1, pvk, acc1);
            acc2 = fmaf(w2, pvk, acc2);
            acc3 = fmaf(w3, pvk, acc3);
            if (kb < 19) { w3 = w2; w2 = w1; w1 = w0; w0 = row[ka0 + 18 - kb]; }
        }
    }

    *reinterpret_cast<float4*>(&sred[gidx * 400 + s * 4]) =
        make_float4(acc0, acc1, acc2, acc3);
    __syncthreads();

    float val = sred[t] + sred[400 + t] + sred[800 + t] + sred[1200 + t];
    g_partial[ib * NPTS + ia * 400 + t] = val;
    __syncthreads();

    sred[t] = val;
    if (t < 112) sred[400 + t] = 0.0f;
    __syncthreads();
    for (int k = 256; k > 32; k >>= 1) {
        if (t < k) sred[t] += sred[t + k];
        __syncthreads();
    }
    if (t < 32) {
        float v = sred[t] + sred[t + 32];
#pragma unroll
        for (int off = 16; off > 0; off >>= 1)
            v += __shfl_down_sync(0xffffffffu, v, off);
        if (t == 0) g_bsum[ia * NGRID + ib] = v;
    }

    // ---------- release this pair; am I the plane finisher? ----------
    __threadfence();
    __syncthreads();
    const int lo = max(0, ia - DA_MAX);
    const int hi = min(NGRID - 1, ia + DA_MAX);
    if (t == 0) {
        int live = hi - lo + 1;
        int c = atomicAdd(&g_cnt_ia[ia], 1);
        sflag = (c == live - 1);
    }
    __syncthreads();
    if (!sflag) return;

    // ---------- plane gather (L2-hot): out[ia-plane] unnormalized ----------
    {
        const int pt = ia * 400 + t;
        float sacc = 0.0f;
#pragma unroll
        for (int k = 0; k < 2 * DA_MAX + 1; k++) {
            int ibb = lo + k;
            if (ibb <= hi) sacc += __ldcg(&g_partial[ibb * NPTS + pt]);
        }
        out[pt] = sacc;
    }
    __threadfence();
    __syncthreads();
    if (t == 0) {
        int q = atomicAdd(&g_cnt_pl, 1);
        sflag = (q == NGRID - 1);
    }
    __syncthreads();
    if (!sflag) return;

    // ---------- global finisher: S, divide, reset ----------
    if (t < 32) {
        float v = 0.0f;
#pragma unroll
        for (int i = 0; i < 13; i++) {        // fixed order over 400 entries
            int idx = t + 32 * i;
            if (idx < 400) {
                int iaa = idx / NGRID;
                int ibb = idx - iaa * NGRID;
                int d   = iaa - ibb;
                if (d >= -DA_MAX && d <= DA_MAX) v += __ldcg(&g_bsum[idx]);
            }
        }
#pragma unroll
        for (int off = 16; off > 0; off >>= 1)
            v += __shfl_xor_sync(0xffffffffu, v, off);
        if (t == 0) sS = v;
    }
    __syncthreads();
    const float invS = 1.0f / sS;

#pragma unroll
    for (int k = 0; k < NGRID; k++) {         // 20 pts/thread, coalesced
        int pt = k * 400 + t;
        out[pt] = __ldcg(&out[pt]) * invS;
    }

    __syncthreads();
    if (t < NGRID) g_cnt_ia[t] = 0;           // replay-safe reset
    if (t == 0)    g_cnt_pl = 0;
    __threadfence();
}

extern "C" void kernel_launch(void* const* d_in, const int* in_sizes, int n_in,
                              void* d_out, int out_size) {
    const float* space_probs = (const float*)d_in[0];  // 8000 floats
    const float* cov_inv     = (const float*)d_in[1];  // 9 floats
    float* out = (float*)d_out;                        // 8000 floats

    kde_kernel<<<dim3(NGRID, NGRID), 400>>>(space_probs, cov_inv, out);
}

// round 13
// speedup vs baseline: 1.3229x; 1.3229x over previous
#include <cuda_runtime.h>

#define NGRID 20
#define NPTS  8000           // 20^3
#define TD    39             // offsets -19..19
#define DA_MAX 7             // da^2/2 > 28 -> plane pruned
#define D2_CUT 28.0f
#define QSCALE 16777216.0f   // 2^24 fixed-point scale (max sum ~1.8e8 < 2^31)

// Scratch (no allocation allowed in kernel_launch)
__device__ int   g_accum[NPTS];             // fixed-point kde accumulator
                                            // (zero-init; self-reset by finish)
__device__ float g_bsum[NGRID * NGRID];     // per live (ia,ib) pair sum

// ---------------------------------------------------------------------------
// Kernel A (R10 conv body, frozen, one change): instead of storing a partial
// plane, each block quantizes its 400 per-point values to 2^24 fixed point
// and REDG-adds them into g_accum. Integer adds commute -> bitwise
// deterministic across block orderings. bsum reduction unchanged.
// ---------------------------------------------------------------------------
__global__ void __launch_bounds__(400) conv_kernel(
    const float* __restrict__ p, const float* __restrict__ cov_inv)
{
    __shared__ __align__(16) float sT[TD * TD + 3];
    __shared__ __align__(16) float sp[NGRID * NGRID];
    __shared__ __align__(16) float sred[1600];

    const int t  = threadIdx.x;
    const int ia = blockIdx.x;
    const int ib = blockIdx.y;
    const int da = ia - ib;

    if (da < -DA_MAX || da > DA_MAX) return;   // pruned: touches nothing

    const float a00 = cov_inv[0], a01 = cov_inv[1], a02 = cov_inv[2];
    const float a11 = cov_inv[4], a12 = cov_inv[5], a22 = cov_inv[8];

    sp[t] = p[ib * 400 + t];

    if (t < 156) {     // table slab via 2-FMUL exp recurrence
        int row = t >> 2, seg = t & 3;
        float dy = (float)(row - 19);
        int   dz0 = -19 + seg * 10;
        int   cnt = (seg == 3) ? 9 : 10;
        float dx = (float)da;
        float c1 = 2.0f * (a02 * dx + a12 * dy);
        float c0 = a00 * dx * dx + 2.0f * a01 * dx * dy + a11 * dy * dy;
        float z  = (float)dz0;
        float g  = expf(-0.5f * (c0 + c1 * z + a22 * z * z));
        float r  = expf(-0.5f * (c1 + a22 * (2.0f * z + 1.0f)));
        float B  = expf(-a22);
        float* dst = &sT[row * TD + (dz0 + 19)];
        for (int i = 0; i < cnt; i++) { dst[i] = g; g *= r; r *= B; }
    }
    __syncthreads();

    const int gidx = t / 100;
    const int s    = t - gidx * 100;
    const int ja   = s / 5;
    const int ka0  = (s - ja * 5) * 4;

    float s00 = a00 - a02 * a02 / a22;
    float s01 = a01 - a02 * a12 / a22;
    float s11 = a11 - a12 * a12 / a22;
    float fx  = (float)da;
    float bq  = s01 * fx;
    float disc = bq * bq - s11 * (s00 * fx * fx - D2_CUT);
    int jb_lo = 0, jb_hi = -1;
    if (disc > 0.0f) {
        float sq  = sqrtf(disc);
        float dyl = (-bq - sq) / s11;
        float dyh = (-bq + sq) / s11;
        jb_lo = max(0,  (int)ceilf ((float)ja - dyh - 0.01f));
        jb_hi = min(19, (int)floorf((float)ja - dyl + 0.01f));
    }

    float acc0 = 0.f, acc1 = 0.f, acc2 = 0.f, acc3 = 0.f;

    for (int jb = jb_lo + gidx; jb <= jb_hi; jb += 4) {
        const float* row = &sT[(ja - jb + 19) * TD];

        float pv[20];
        {
            const float4* pr4 = reinterpret_cast<const float4*>(&sp[jb * NGRID]);
#pragma unroll
            for (int u = 0; u < 5; u++) {
                float4 v = pr4[u];
                pv[4*u] = v.x; pv[4*u+1] = v.y; pv[4*u+2] = v.z; pv[4*u+3] = v.w;
            }
        }

        float w0 = row[ka0 + 19];
        float w1 = row[ka0 + 20];
        float w2 = row[ka0 + 21];
        float w3 = row[ka0 + 22];
#pragma unroll
        for (int kb = 0; kb < 20; kb++) {
            float pvk = pv[kb];
            acc0 = fmaf(w0, pvk, acc0);
            acc1 = fmaf(w1, pvk, acc1);
            acc2 = fmaf(w2, pvk, acc2);
            acc3 = fmaf(w3, pvk, acc3);
            if (kb < 19) { w3 = w2; w2 = w1; w1 = w0; w0 = row[ka0 + 18 - kb]; }
        }
    }

    *reinterpret_cast<float4*>(&sred[gidx * 400 + s * 4]) =
        make_float4(acc0, acc1, acc2, acc3);
    __syncthreads();

    // fold the 4 jb-groups in fixed order, accumulate into fixed point
    float val = sred[t] + sred[400 + t] + sred[800 + t] + sred[1200 + t];
    atomicAdd(&g_accum[ia * 400 + t], __float2int_rn(val * QSCALE));
    __syncthreads();

    // block sum (deterministic tree)
    sred[t] = val;
    if (t < 112) sred[400 + t] = 0.0f;
    __syncthreads();
    for (int k = 256; k > 32; k >>= 1) {
        if (t < k) sred[t] += sred[t + k];
        __syncthreads();
    }
    if (t < 32) {
        float v = sred[t] + sred[t + 32];
#pragma unroll
        for (int off = 16; off > 0; off >>= 1)
            v += __shfl_down_sync(0xffffffffu, v, off);
        if (t == 0) g_bsum[ia * NGRID + ib] = v;
    }
}

// ---------------------------------------------------------------------------
// Kernel B: dequantize + normalize + self-reset. 64 blocks x 128 threads,
// one point per thread. S folded warp-redundantly in fixed order over the
// live pairs only (pruned g_bsum entries are never written).
// ---------------------------------------------------------------------------
__global__ void __launch_bounds__(128) finish_kernel(float* __restrict__ out) {
    const int t    = threadIdx.x;
    const int lane = t & 31;
    const int pt   = blockIdx.x * 128 + t;

    // issue the accumulator load first (independent of S)
    int q = 0;
    if (pt < NPTS) q = g_accum[pt];

    // warp-redundant fixed-order fold over live (ia,ib) pairs
    float v = 0.0f;
#pragma unroll
    for (int i = 0; i < 13; i++) {               // 13*32 = 416 >= 400
        int idx = lane + 32 * i;
        if (idx < 400) {
            int iaa = idx / NGRID;
            int ibb = idx - iaa * NGRID;
            int d   = iaa - ibb;
            if (d >= -DA_MAX && d <= DA_MAX) v += g_bsum[idx];
        }
    }
#pragma unroll
    for (int off = 16; off > 0; off >>= 1)
        v += __shfl_xor_sync(0xffffffffu, v, off);
    const float S = v;

    if (pt >= NPTS) return;
    out[pt] = (float)q * ((1.0f / QSCALE) / S);
    g_accum[pt] = 0;                              // replay-safe reset
}

extern "C" void kernel_launch(void* const* d_in, const int* in_sizes, int n_in,
                              void* d_out, int out_size) {
    const float* space_probs = (const float*)d_in[0];  // 8000 floats
    const float* cov_inv     = (const float*)d_in[1];  // 9 floats
    float* out = (float*)d_out;                        // 8000 floats

    conv_kernel  <<<dim3(NGRID, NGRID), 400>>>(space_probs, cov_inv);
    finish_kernel<<<64, 128>>>(out);
}